// round 9
// baseline (speedup 1.0000x reference)
#include <cuda_runtime.h>
#include <cfloat>
#include <math.h>

#define FULL 0xffffffffu

constexpr int B = 4;
constexpr int N = 8192;
constexpr int M = 4096;
constexpr int F = 64;
constexpr int K = 16;
constexpr float MIN_SIGMA = 1e-4f;

constexpr int   NBX   = 128;      // x-bins
constexpr int   NYB   = 16;       // y-sub-bins per x-bin
constexpr int   NBINS = NBX * NYB;
constexpr float XLO   = -3.2f;
constexpr float XW    = 0.05f;
constexpr float XINVW = 20.0f;
constexpr float YLO   = -3.2f;
constexpr float YW    = 0.4f;
constexpr float YINVW = 2.5f;
constexpr float EPSP  = 1e-4f;    // conservative pad (x gaps / y windows)
constexpr float RY0   = 0.35f;    // pass-1 home-bin y heuristic (exactness-neutral)

// Scratch (no allocations allowed)
__device__ float  g_featT[(size_t)B * N * F];    // (B,N,F) transposed features
__device__ float4 g_sorted[B * N];               // points {x,y,z,bits(n)}, (xb,yb)-sorted
__device__ float4 g_qsorted[B * M];              // queries {x,y,z,bits(m)}, (xb,yb)-sorted
__device__ int    g_start[B * (NBINS + 1)];      // point bin offsets
__device__ int    g_task[B];                     // dynamic task counters

// ---------------------------------------------------------------------------
__device__ __forceinline__ int xbinf(float x) {
    return min(NBX - 1, max(0, (int)floorf((x - XLO) * XINVW)));
}
__device__ __forceinline__ int ybinf(float y) {
    return min(NYB - 1, max(0, (int)floorf((y - YLO) * YINVW)));
}
__device__ __forceinline__ int bin2(float x, float y) {
    return xbinf(x) * NYB + ybinf(y);
}

// ---------------------------------------------------------------------------
// Fused build: one CTA per (kind, batch). smem histogram (2048 bins) +
// block scan + smem-cursor scatter. Zeroes task counters for this replay.
// ---------------------------------------------------------------------------
__global__ void __launch_bounds__(1024, 1)
build_kernel(const float* __restrict__ pc, const float* __restrict__ qc) {
    __shared__ int cnt[NBINS];
    __shared__ int cur[NBINS];
    __shared__ int wsum[32];
    const int g = blockIdx.x;            // 0..3: points, 4..7: queries
    const bool isQ = g >= B;
    const int b = isQ ? g - B : g;
    const int n = isQ ? M : N;
    const float* src = isQ ? qc + (size_t)b * 3 * M : pc + (size_t)b * 3 * N;
    float4* dst = isQ ? g_qsorted + (size_t)b * M : g_sorted + (size_t)b * N;
    const int tid = threadIdx.x;
    const int lane = tid & 31, wid = tid >> 5;

    if (g == 0 && tid < B) g_task[tid] = 0;

    for (int i = tid; i < NBINS; i += 1024) cnt[i] = 0;
    __syncthreads();
    for (int i = tid; i < n; i += 1024)
        atomicAdd(&cnt[bin2(src[i], src[n + i])], 1);
    __syncthreads();

    // block exclusive scan, 2 bins per thread
    const int a0 = cnt[2 * tid], a1 = cnt[2 * tid + 1];
    const int s = a0 + a1;
    int inc = s;
    #pragma unroll
    for (int off = 1; off < 32; off <<= 1) {
        int nb = __shfl_up_sync(FULL, inc, off);
        if (lane >= off) inc += nb;
    }
    if (lane == 31) wsum[wid] = inc;
    __syncthreads();
    if (wid == 0) {
        int v = wsum[lane];
        #pragma unroll
        for (int off = 1; off < 32; off <<= 1) {
            int nb = __shfl_up_sync(FULL, v, off);
            if (lane >= off) v += nb;
        }
        wsum[lane] = v;
    }
    __syncthreads();
    const int excl = (wid ? wsum[wid - 1] : 0) + inc - s;
    cur[2 * tid] = excl;
    cur[2 * tid + 1] = excl + a0;
    if (!isQ) {
        g_start[b * (NBINS + 1) + 2 * tid]     = excl;
        g_start[b * (NBINS + 1) + 2 * tid + 1] = excl + a0;
        if (tid == 1023) g_start[b * (NBINS + 1) + NBINS] = excl + a0 + a1;
    }
    __syncthreads();
    for (int i = tid; i < n; i += 1024) {
        const float x = src[i], y = src[n + i], z = src[2 * n + i];
        const int pos = atomicAdd(&cur[bin2(x, y)], 1);
        dst[pos] = make_float4(x, y, z, __int_as_float(i));
    }
}

// ---------------------------------------------------------------------------
__global__ void transpose_feat_kernel(const float* __restrict__ feat) {
    __shared__ float tile[32][33];
    const int b  = blockIdx.z;
    const int n0 = blockIdx.x * 32;
    const int f0 = blockIdx.y * 32;
    const int tx = threadIdx.x, ty = threadIdx.y;
    #pragma unroll
    for (int i = ty; i < 32; i += 8)
        tile[i][tx] = feat[(size_t)b * F * N + (size_t)(f0 + i) * N + (n0 + tx)];
    __syncthreads();
    #pragma unroll
    for (int i = ty; i < 32; i += 8)
        g_featT[((size_t)b * N + (n0 + i)) * F + (f0 + tx)] = tile[tx][i];
}

// ---------------------------------------------------------------------------
// Warp-cooperative top-K insert into 16-entry sorted list in lanes
// [base, base+16); candidates from any lane; threshold warp-uniform.
// ---------------------------------------------------------------------------
__device__ __forceinline__ void topk_insert(float s, int pidx, int lane,
                                            float& val, int& idx,
                                            float& threshold, int base) {
    unsigned bal = __ballot_sync(FULL, s < threshold);
    while (bal) {
        const int src = __ffs(bal) - 1;
        bal &= bal - 1;
        const float cs = __shfl_sync(FULL, s, src);
        if (cs < threshold) {
            const int ci = __shfl_sync(FULL, pidx, src);
            const bool mine = (unsigned)(lane - base) < (unsigned)K;
            const unsigned less = __ballot_sync(FULL, mine && (val <= cs));
            const int pos = base + __popc(less);
            const float ot = __shfl_up_sync(FULL, val, 1);
            const int   oi = __shfl_up_sync(FULL, idx, 1);
            if (mine) {
                if (lane == pos)     { val = cs; idx = ci; }
                else if (lane > pos) { val = ot; idx = oi; }
            }
            threshold = __shfl_sync(FULL, val, base + K - 1);
        }
    }
}

// ---------------------------------------------------------------------------
// Query kernel: one warp handles TWO (x,y)-adjacent queries per dynamic task.
// Home x-bin: y-window around qy first (fast th convergence), then patch the
// full th-window; then x expansion L/R with per-bin y-pruning.
// ---------------------------------------------------------------------------
__global__ void __launch_bounds__(1024, 1)
soft_projection_query(const float* __restrict__ temp,
                      float* __restrict__ out) {
    extern __shared__ char smraw[];
    float4* spts = (float4*)smraw;                                 // 128KB
    int*   cst = (int*)(smraw + (size_t)N * sizeof(float4));       // 2049 ints
    float* stw = (float*)(smraw + (size_t)N * sizeof(float4) + 8208);
    int*   sti = (int*)  (smraw + (size_t)N * sizeof(float4) + 8208 + 4096);

    const int b = blockIdx.y;
    for (int i = threadIdx.x; i < N; i += blockDim.x) spts[i] = g_sorted[b * N + i];
    for (int i = threadIdx.x; i < NBINS + 1; i += blockDim.x)
        cst[i] = g_start[b * (NBINS + 1) + i];
    __syncthreads();

    const float t = *temp;
    const float inv_sigma = 1.0f / fmaxf(t * t, MIN_SIGMA);

    const int lane = threadIdx.x & 31;
    const int warp = threadIdx.x >> 5;
    float* mysw = stw + warp * 32;
    int*   mysi = sti + warp * 32;

    float* out_pts  = out + (size_t)b * 3 * M;
    float* out_feat = out + (size_t)B * 3 * M + (size_t)b * F * M;
    const float* featb = g_featT + (size_t)b * N * F;
    const float4* qs = g_qsorted + (size_t)b * M;

    constexpr int NT = M / 2;
    while (true) {
        int pos;
        if (lane == 0) pos = atomicAdd(&g_task[b], 1);
        pos = __shfl_sync(FULL, pos, 0);
        if (pos >= NT) break;
        const int task = (NT / 2) + ((pos & 1) ? -((pos + 1) >> 1) : (pos >> 1));

        const float4 QA = qs[2 * task];
        const float4 QB = qs[2 * task + 1];
        const int mA = __float_as_int(QA.w);
        const int mB = __float_as_int(QB.w);

        float val = FLT_MAX;
        int   idx = 0;
        float thA = FLT_MAX, thB = FLT_MAX;
        bool  init = false;

        // scan [s,e): first call does 32-pt bitonic init, then 64-pt chunks
        auto scan_raw = [&](int s, int e) {
            if (s >= e) return;
            if (!init) {
                const int p = s + lane;
                float dA = FLT_MAX, dB = FLT_MAX;
                int pA = p, pB = p;
                if (p < e) {
                    const float4 pt = spts[p];
                    const float aX = pt.x - QA.x, aY = pt.y - QA.y, aZ = pt.z - QA.z;
                    const float bX = pt.x - QB.x, bY = pt.y - QB.y, bZ = pt.z - QB.z;
                    dA = fmaf(aX, aX, fmaf(aY, aY, aZ * aZ));
                    dB = fmaf(bX, bX, fmaf(bY, bY, bZ * bZ));
                }
                #pragma unroll
                for (int k = 2; k <= 32; k <<= 1) {
                    #pragma unroll
                    for (int j = k >> 1; j > 0; j >>= 1) {
                        const float ovA = __shfl_xor_sync(FULL, dA, j);
                        const int   oiA = __shfl_xor_sync(FULL, pA, j);
                        const float ovB = __shfl_xor_sync(FULL, dB, j);
                        const int   oiB = __shfl_xor_sync(FULL, pB, j);
                        const bool ks = ((lane & j) == 0) == ((lane & k) == 0);
                        if (ks ? (ovA < dA) : (ovA > dA)) { dA = ovA; pA = oiA; }
                        if (ks ? (ovB < dB) : (ovB > dB)) { dB = ovB; pB = oiB; }
                    }
                }
                const float dBs = __shfl_sync(FULL, dB, lane - 16);
                const int   pBs = __shfl_sync(FULL, pB, lane - 16);
                val = (lane < 16) ? dA : dBs;
                idx = (lane < 16) ? pA : pBs;
                thA = __shfl_sync(FULL, val, K - 1);
                thB = __shfl_sync(FULL, val, 16 + K - 1);
                init = true;
                s = min(s + 32, e);
            }
            for (int p0 = s; p0 < e; p0 += 64) {
                const int q0 = p0 + lane, q1 = p0 + lane + 32;
                float dA0 = FLT_MAX, dA1 = FLT_MAX, dB0 = FLT_MAX, dB1 = FLT_MAX;
                if (q0 < e) {
                    const float4 pt = spts[q0];
                    const float aX = pt.x - QA.x, aY = pt.y - QA.y, aZ = pt.z - QA.z;
                    const float bX = pt.x - QB.x, bY = pt.y - QB.y, bZ = pt.z - QB.z;
                    dA0 = fmaf(aX, aX, fmaf(aY, aY, aZ * aZ));
                    dB0 = fmaf(bX, bX, fmaf(bY, bY, bZ * bZ));
                }
                if (q1 < e) {
                    const float4 pt = spts[q1];
                    const float aX = pt.x - QA.x, aY = pt.y - QA.y, aZ = pt.z - QA.z;
                    const float bX = pt.x - QB.x, bY = pt.y - QB.y, bZ = pt.z - QB.z;
                    dA1 = fmaf(aX, aX, fmaf(aY, aY, aZ * aZ));
                    dB1 = fmaf(bX, bX, fmaf(bY, bY, bZ * bZ));
                }
                const bool cc = (fminf(dA0, dA1) < thA) | (fminf(dB0, dB1) < thB);
                if (__any_sync(FULL, cc)) {
                    topk_insert(dA0, q0, lane, val, idx, thA, 0);
                    topk_insert(dA1, q1, lane, val, idx, thA, 0);
                    topk_insert(dB0, q0, lane, val, idx, thB, 16);
                    topk_insert(dB1, q1, lane, val, idx, thB, 16);
                }
            }
        };

        // union y-window for an x-bin given per-query x-gap^2 (clamped >= 0)
        auto bin_window = [&](float gxA2, float gxB2, int& lo, int& hi) -> bool {
            lo = NYB; hi = -1;
            const float aA = thA - gxA2;
            if (aA > 0.0f) {
                const float ry = sqrtf(aA) + EPSP;
                lo = min(lo, max(0, min(NYB - 1, (int)floorf((QA.y - ry - YLO) * YINVW))));
                hi = max(hi, max(0, min(NYB - 1, (int)floorf((QA.y + ry - YLO) * YINVW))));
            }
            const float aB = thB - gxB2;
            if (aB > 0.0f) {
                const float ry = sqrtf(aB) + EPSP;
                lo = min(lo, max(0, min(NYB - 1, (int)floorf((QB.y - ry - YLO) * YINVW))));
                hi = max(hi, max(0, min(NYB - 1, (int)floorf((QB.y + ry - YLO) * YINVW))));
            }
            return lo <= hi;
        };

        const int h = xbinf(0.5f * (QA.x + QB.x));

        // ---- home bin pass 1: heuristic y-window (near points first) ----
        const int p1lo = max(0, min(NYB - 1,
            (int)floorf((fminf(QA.y, QB.y) - RY0 - YLO) * YINVW)));
        const int p1hi = max(0, min(NYB - 1,
            (int)floorf((fmaxf(QA.y, QB.y) + RY0 - YLO) * YINVW)));
        scan_raw(cst[h * NYB + p1lo], cst[h * NYB + p1hi + 1]);

        // ---- home bin pass 2: patch full th-derived window ----
        {
            int lo, hi;
            if (bin_window(0.0f, 0.0f, lo, hi)) {
                if (lo < p1lo) scan_raw(cst[h * NYB + lo], cst[h * NYB + p1lo]);
                if (hi > p1hi) scan_raw(cst[h * NYB + p1hi + 1], cst[h * NYB + hi + 1]);
            }
        }

        // ---- x expansion: left then right, dynamic boundary + y-prune ----
        for (int l = h - 1; l >= 0; l--) {
            const float edge = XLO + (l + 1) * XW;
            const float gA = QA.x - edge - EPSP;
            const float gB = QB.x - edge - EPSP;
            const float gA2 = (gA > 0.0f) ? gA * gA : 0.0f;
            const float gB2 = (gB > 0.0f) ? gB * gB : 0.0f;
            if (gA2 >= thA && gB2 >= thB && gA > 0.0f && gB > 0.0f) break;
            int lo, hi;
            if (bin_window(gA2, gB2, lo, hi))
                scan_raw(cst[l * NYB + lo], cst[l * NYB + hi + 1]);
        }
        for (int r = h + 1; r < NBX; r++) {
            const float edge = XLO + r * XW;
            const float gA = edge - QA.x - EPSP;
            const float gB = edge - QB.x - EPSP;
            const float gA2 = (gA > 0.0f) ? gA * gA : 0.0f;
            const float gB2 = (gB > 0.0f) ? gB * gB : 0.0f;
            if (gA2 >= thA && gB2 >= thB && gA > 0.0f && gB > 0.0f) break;
            int lo, hi;
            if (bin_window(gA2, gB2, lo, hi))
                scan_raw(cst[r * NYB + lo], cst[r * NYB + hi + 1]);
        }

        // ---- softmax per half-warp (unsorted-safe: only min + sum needed) ----
        const int base = lane & 16;
        float s_min = val;
        #pragma unroll
        for (int o = 8; o; o >>= 1) s_min = fminf(s_min, __shfl_xor_sync(FULL, s_min, o));
        (void)base;
        const float e = __expf(-(val - s_min) * inv_sigma);
        float esum = e;
        #pragma unroll
        for (int o = 8; o; o >>= 1) esum += __shfl_xor_sync(FULL, esum, o);
        const float w = e / esum;

        // ---- projected points ----
        const float4 gp = spts[idx];
        float wx = w * gp.x, wy = w * gp.y, wz = w * gp.z;
        #pragma unroll
        for (int o = 8; o; o >>= 1) {
            wx += __shfl_xor_sync(FULL, wx, o);
            wy += __shfl_xor_sync(FULL, wy, o);
            wz += __shfl_xor_sync(FULL, wz, o);
        }
        if (lane == 0) {
            out_pts[mA]         = wx;
            out_pts[M + mA]     = wy;
            out_pts[2 * M + mA] = wz;
        } else if (lane == 16) {
            out_pts[mB]         = wx;
            out_pts[M + mB]     = wy;
            out_pts[2 * M + mB] = wz;
        }

        // ---- features: stage (w, idx) in smem, broadcast-read ----
        const int og = __float_as_int(gp.w);
        mysw[lane] = w;
        mysi[lane] = og;
        __syncwarp();
        float a0 = 0.f, a1 = 0.f, c0 = 0.f, c1 = 0.f;
        #pragma unroll
        for (int j = 0; j < K; j++) {
            const float wj = mysw[j];
            const int   gj = mysi[j];
            const float2 f2 = *reinterpret_cast<const float2*>(
                featb + (size_t)gj * F + lane * 2);
            a0 = fmaf(wj, f2.x, a0);
            a1 = fmaf(wj, f2.y, a1);
        }
        #pragma unroll
        for (int j = 16; j < 16 + K; j++) {
            const float wj = mysw[j];
            const int   gj = mysi[j];
            const float2 f2 = *reinterpret_cast<const float2*>(
                featb + (size_t)gj * F + lane * 2);
            c0 = fmaf(wj, f2.x, c0);
            c1 = fmaf(wj, f2.y, c1);
        }
        __syncwarp();
        out_feat[(size_t)(2 * lane) * M + mA]     = a0;
        out_feat[(size_t)(2 * lane + 1) * M + mA] = a1;
        out_feat[(size_t)(2 * lane) * M + mB]     = c0;
        out_feat[(size_t)(2 * lane + 1) * M + mB] = c1;
    }
}

// ---------------------------------------------------------------------------
extern "C" void kernel_launch(void* const* d_in, const int* in_sizes, int n_in,
                              void* d_out, int out_size) {
    const float* pc   = (const float*)d_in[0];  // (B,3,N)
    const float* qc   = (const float*)d_in[1];  // (B,3,M)
    const float* pf   = (const float*)d_in[2];  // (B,F,N)
    const float* temp = (const float*)d_in[3];  // scalar
    float* out = (float*)d_out;                 // (B,3,M) ++ (B,F,M)
    (void)in_sizes; (void)n_in; (void)out_size;

    const int smem = N * (int)sizeof(float4) + 8208 + 4096 + 4096;
    cudaFuncSetAttribute(soft_projection_query,
                         cudaFuncAttributeMaxDynamicSharedMemorySize, smem);

    build_kernel<<<2 * B, 1024>>>(pc, qc);
    transpose_feat_kernel<<<dim3(N / 32, F / 32, B), dim3(32, 8)>>>(pf);
    soft_projection_query<<<dim3(37, B), 1024, smem>>>(temp, out);
}

// round 10
// speedup vs baseline: 1.1228x; 1.1228x over previous
#include <cuda_runtime.h>
#include <cfloat>
#include <math.h>

#define FULL 0xffffffffu

constexpr int B = 4;
constexpr int N = 8192;
constexpr int M = 4096;
constexpr int F = 64;
constexpr int K = 16;
constexpr float MIN_SIGMA = 1e-4f;

constexpr int   NB    = 128;      // x-bins
constexpr float XLO   = -3.2f;
constexpr float XW    = 0.05f;
constexpr float XINVW = 20.0f;
constexpr float EPSP  = 1e-4f;    // conservative pad on bin-edge gaps

// Scratch (no allocations allowed)
__device__ float  g_featT[(size_t)B * N * F];   // (B,N,F) transposed features
__device__ float4 g_sorted[B * N];              // points {x,y,z,bits(n)}, x-bin-sorted
__device__ float4 g_qsorted[B * M];             // queries {x,y,z,bits(m)}, x-bin-sorted
__device__ int    g_start[B * (NB + 1)];        // point bin offsets
__device__ int    g_task[B];                    // dynamic task counters

// ---------------------------------------------------------------------------
__device__ __forceinline__ int xbin(float x) {
    return min(NB - 1, max(0, (int)floorf((x - XLO) * XINVW)));
}

// ---------------------------------------------------------------------------
// Fused build: one CTA per (kind, batch). smem histogram + warp scan +
// smem-cursor scatter. Zeroes the task counters for this replay.
// ---------------------------------------------------------------------------
__global__ void __launch_bounds__(1024, 1)
build_kernel(const float* __restrict__ pc, const float* __restrict__ qc) {
    __shared__ int cnt[NB];
    __shared__ int cur[NB];
    const int g = blockIdx.x;            // 0..3: points, 4..7: queries
    const bool isQ = g >= B;
    const int b = isQ ? g - B : g;
    const int n = isQ ? M : N;
    const float* src = isQ ? qc + (size_t)b * 3 * M : pc + (size_t)b * 3 * N;
    float4* dst = isQ ? g_qsorted + (size_t)b * M : g_sorted + (size_t)b * N;
    const int tid = threadIdx.x;

    if (g == 0 && tid < B) g_task[tid] = 0;

    for (int i = tid; i < NB; i += blockDim.x) cnt[i] = 0;
    __syncthreads();
    for (int i = tid; i < n; i += blockDim.x)
        atomicAdd(&cnt[xbin(src[i])], 1);
    __syncthreads();
    if (tid < 32) {   // warp 0: exclusive scan of 128 bins, 4 per lane
        const int lane = tid;
        const int o = lane * 4;
        int v0 = cnt[o], v1 = cnt[o + 1], v2 = cnt[o + 2], v3 = cnt[o + 3];
        const int tsum = v0 + v1 + v2 + v3;
        int inc = tsum;
        #pragma unroll
        for (int off = 1; off < 32; off <<= 1) {
            int nb = __shfl_up_sync(FULL, inc, off);
            if (lane >= off) inc += nb;
        }
        int acc = inc - tsum;
        cur[o] = acc;
        if (!isQ) g_start[b * (NB + 1) + o] = acc;
        acc += v0;
        cur[o + 1] = acc;
        if (!isQ) g_start[b * (NB + 1) + o + 1] = acc;
        acc += v1;
        cur[o + 2] = acc;
        if (!isQ) g_start[b * (NB + 1) + o + 2] = acc;
        acc += v2;
        cur[o + 3] = acc;
        if (!isQ) g_start[b * (NB + 1) + o + 3] = acc;
        acc += v3;
        if (!isQ && lane == 31) g_start[b * (NB + 1) + NB] = acc;
    }
    __syncthreads();
    for (int i = tid; i < n; i += blockDim.x) {
        const float x = src[i], y = src[n + i], z = src[2 * n + i];
        const int pos = atomicAdd(&cur[xbin(x)], 1);
        dst[pos] = make_float4(x, y, z, __int_as_float(i));
    }
}

// ---------------------------------------------------------------------------
__global__ void transpose_feat_kernel(const float* __restrict__ feat) {
    __shared__ float tile[32][33];
    const int b  = blockIdx.z;
    const int n0 = blockIdx.x * 32;
    const int f0 = blockIdx.y * 32;
    const int tx = threadIdx.x, ty = threadIdx.y;
    #pragma unroll
    for (int i = ty; i < 32; i += 8)
        tile[i][tx] = feat[(size_t)b * F * N + (size_t)(f0 + i) * N + (n0 + tx)];
    __syncthreads();
    #pragma unroll
    for (int i = ty; i < 32; i += 8)
        g_featT[((size_t)b * N + (n0 + i)) * F + (f0 + tx)] = tile[tx][i];
}

// ---------------------------------------------------------------------------
// Streamlined warp-cooperative top-K insert. No per-candidate threshold
// broadcast: inserting a candidate that is not among the 16 smallest seen
// is a natural no-op (insertion position lands at base+16, nobody writes).
// Caller refreshes the warp-uniform threshold after the batch.
// ---------------------------------------------------------------------------
__device__ __forceinline__ void topk_insert(float s, int pidx, int lane,
                                            float& val, int& idx,
                                            float threshold, int base) {
    unsigned bal = __ballot_sync(FULL, s < threshold);
    const bool mine = (unsigned)(lane - base) < (unsigned)K;
    while (bal) {
        const int src = __ffs(bal) - 1;
        bal &= bal - 1;
        const float cs = __shfl_sync(FULL, s, src);
        const int   ci = __shfl_sync(FULL, pidx, src);
        const unsigned less = __ballot_sync(FULL, mine && (val <= cs));
        const int pos = base + __popc(less);
        const float ot = __shfl_up_sync(FULL, val, 1);
        const int   oi = __shfl_up_sync(FULL, idx, 1);
        if (mine) {
            if (lane == pos)     { val = cs; idx = ci; }
            else if (lane > pos) { val = ot; idx = oi; }
        }
    }
}

// ---------------------------------------------------------------------------
// Query kernel: one warp handles TWO x-adjacent queries per dynamic task
// (center-out LPT order). 32-pt bitonic seed; bin-wise dynamic-boundary scan.
// Query A's top-16 in lanes 0..15, query B's in lanes 16..31.
// ---------------------------------------------------------------------------
__global__ void __launch_bounds__(1024, 1)
soft_projection_query(const float* __restrict__ temp,
                      float* __restrict__ out) {
    extern __shared__ char smraw[];
    float4* spts = (float4*)smraw;                                   // 128KB
    int*   cst = (int*)(smraw + (size_t)N * sizeof(float4));         // 129 ints
    float* stw = (float*)(smraw + (size_t)N * sizeof(float4) + 516);     // 4KB
    int*   sti = (int*)  (smraw + (size_t)N * sizeof(float4) + 516 + 4096);

    const int b = blockIdx.y;
    for (int i = threadIdx.x; i < N; i += blockDim.x) spts[i] = g_sorted[b * N + i];
    for (int i = threadIdx.x; i < NB + 1; i += blockDim.x)
        cst[i] = g_start[b * (NB + 1) + i];
    __syncthreads();

    const float t = *temp;
    const float inv_sigma = 1.0f / fmaxf(t * t, MIN_SIGMA);

    const int lane = threadIdx.x & 31;
    const int warp = threadIdx.x >> 5;
    float* mysw = stw + warp * 32;
    int*   mysi = sti + warp * 32;

    float* out_pts  = out + (size_t)b * 3 * M;
    float* out_feat = out + (size_t)B * 3 * M + (size_t)b * F * M;
    const float* featb = g_featT + (size_t)b * N * F;
    const float4* qs = g_qsorted + (size_t)b * M;

    constexpr int NT = M / 2;         // 2048 tasks per batch
    while (true) {
        int pos;
        if (lane == 0) pos = atomicAdd(&g_task[b], 1);
        pos = __shfl_sync(FULL, pos, 0);
        if (pos >= NT) break;
        // center-out order (longest tasks first)
        const int task = (NT / 2) + ((pos & 1) ? -((pos + 1) >> 1) : (pos >> 1));

        const float4 QA = qs[2 * task];
        const float4 QB = qs[2 * task + 1];
        const int mA = __float_as_int(QA.w);
        const int mB = __float_as_int(QB.w);

        float val, thA, thB;
        int   idx;

        // ---- seed: 32 points at the home bin start, dual bitonic sort ----
        const int h = xbin(0.5f * (QA.x + QB.x));
        const int s0 = min(cst[h], N - 32);
        {
            const float4 pt = spts[s0 + lane];
            const float aX = pt.x - QA.x, aY = pt.y - QA.y, aZ = pt.z - QA.z;
            const float bX = pt.x - QB.x, bY = pt.y - QB.y, bZ = pt.z - QB.z;
            float dA = fmaf(aX, aX, fmaf(aY, aY, aZ * aZ));
            float dB = fmaf(bX, bX, fmaf(bY, bY, bZ * bZ));
            int pA = s0 + lane, pB = s0 + lane;
            #pragma unroll
            for (int k = 2; k <= 32; k <<= 1) {
                #pragma unroll
                for (int j = k >> 1; j > 0; j >>= 1) {
                    const float ovA = __shfl_xor_sync(FULL, dA, j);
                    const int   oiA = __shfl_xor_sync(FULL, pA, j);
                    const float ovB = __shfl_xor_sync(FULL, dB, j);
                    const int   oiB = __shfl_xor_sync(FULL, pB, j);
                    const bool ks = ((lane & j) == 0) == ((lane & k) == 0);
                    if (ks ? (ovA < dA) : (ovA > dA)) { dA = ovA; pA = oiA; }
                    if (ks ? (ovB < dB) : (ovB > dB)) { dB = ovB; pB = oiB; }
                }
            }
            const float dBs = __shfl_sync(FULL, dB, lane - 16);
            const int   pBs = __shfl_sync(FULL, pB, lane - 16);
            val = (lane < 16) ? dA : dBs;
            idx = (lane < 16) ? pA : pBs;
            thA = __shfl_sync(FULL, val, K - 1);
            thB = __shfl_sync(FULL, val, 16 + K - 1);
        }

        // ---- scan one range [s,e) in 64-pt chunks, both queries ----
        auto scan_raw = [&](int s, int e) {
            for (int p0 = s; p0 < e; p0 += 64) {
                const int q0 = p0 + lane, q1 = p0 + lane + 32;
                float dA0 = FLT_MAX, dA1 = FLT_MAX, dB0 = FLT_MAX, dB1 = FLT_MAX;
                if (q0 < e) {
                    const float4 pt = spts[q0];
                    const float aX = pt.x - QA.x, aY = pt.y - QA.y, aZ = pt.z - QA.z;
                    const float bX = pt.x - QB.x, bY = pt.y - QB.y, bZ = pt.z - QB.z;
                    dA0 = fmaf(aX, aX, fmaf(aY, aY, aZ * aZ));
                    dB0 = fmaf(bX, bX, fmaf(bY, bY, bZ * bZ));
                }
                if (q1 < e) {
                    const float4 pt = spts[q1];
                    const float aX = pt.x - QA.x, aY = pt.y - QA.y, aZ = pt.z - QA.z;
                    const float bX = pt.x - QB.x, bY = pt.y - QB.y, bZ = pt.z - QB.z;
                    dA1 = fmaf(aX, aX, fmaf(aY, aY, aZ * aZ));
                    dB1 = fmaf(bX, bX, fmaf(bY, bY, bZ * bZ));
                }
                const bool cc = (fminf(dA0, dA1) < thA) | (fminf(dB0, dB1) < thB);
                if (__any_sync(FULL, cc)) {
                    topk_insert(dA0, q0, lane, val, idx, thA, 0);
                    topk_insert(dA1, q1, lane, val, idx, thA, 0);
                    topk_insert(dB0, q0, lane, val, idx, thB, 16);
                    topk_insert(dB1, q1, lane, val, idx, thB, 16);
                    thA = __shfl_sync(FULL, val, K - 1);       // refresh once
                    thB = __shfl_sync(FULL, val, 16 + K - 1);  // per chunk
                }
            }
        };
        // range minus the seed block [s0, s0+32)
        auto scan_range = [&](int s, int e) {
            scan_raw(s, min(e, s0));
            scan_raw(max(s, s0 + 32), e);
        };

        scan_range(cst[h], cst[h + 1]);   // home bin
        for (int l = h - 1; l >= 0; l--) {          // left expansion
            const float edge = XLO + (l + 1) * XW;
            const float gA = QA.x - edge - EPSP;
            const float gB = QB.x - edge - EPSP;
            const bool stopA = (gA > 0.0f) && (gA * gA >= thA);
            const bool stopB = (gB > 0.0f) && (gB * gB >= thB);
            if (stopA && stopB) break;
            scan_range(cst[l], cst[l + 1]);
        }
        for (int r = h + 1; r < NB; r++) {          // right expansion
            const float edge = XLO + r * XW;
            const float gA = edge - QA.x - EPSP;
            const float gB = edge - QB.x - EPSP;
            const bool stopA = (gA > 0.0f) && (gA * gA >= thA);
            const bool stopB = (gB > 0.0f) && (gB * gB >= thB);
            if (stopA && stopB) break;
            scan_range(cst[r], cst[r + 1]);
        }

        // ---- softmax per half-warp ----
        const int base = lane & 16;
        const float s_min = __shfl_sync(FULL, val, base);
        const float e = __expf(-(val - s_min) * inv_sigma);
        float esum = e;
        #pragma unroll
        for (int o = 8; o; o >>= 1) esum += __shfl_xor_sync(FULL, esum, o);
        const float w = e / esum;

        // ---- projected points ----
        const float4 gp = spts[idx];
        float wx = w * gp.x, wy = w * gp.y, wz = w * gp.z;
        #pragma unroll
        for (int o = 8; o; o >>= 1) {
            wx += __shfl_xor_sync(FULL, wx, o);
            wy += __shfl_xor_sync(FULL, wy, o);
            wz += __shfl_xor_sync(FULL, wz, o);
        }
        if (lane == 0) {
            out_pts[mA]         = wx;
            out_pts[M + mA]     = wy;
            out_pts[2 * M + mA] = wz;
        } else if (lane == 16) {
            out_pts[mB]         = wx;
            out_pts[M + mB]     = wy;
            out_pts[2 * M + mB] = wz;
        }

        // ---- features: stage (w, idx) in smem, broadcast-read ----
        const int og = __float_as_int(gp.w);
        mysw[lane] = w;
        mysi[lane] = og;
        __syncwarp();
        float a0 = 0.f, a1 = 0.f, c0 = 0.f, c1 = 0.f;
        #pragma unroll
        for (int j = 0; j < K; j++) {
            const float wj = mysw[j];
            const int   gj = mysi[j];
            const float2 f2 = *reinterpret_cast<const float2*>(
                featb + (size_t)gj * F + lane * 2);
            a0 = fmaf(wj, f2.x, a0);
            a1 = fmaf(wj, f2.y, a1);
        }
        #pragma unroll
        for (int j = 16; j < 16 + K; j++) {
            const float wj = mysw[j];
            const int   gj = mysi[j];
            const float2 f2 = *reinterpret_cast<const float2*>(
                featb + (size_t)gj * F + lane * 2);
            c0 = fmaf(wj, f2.x, c0);
            c1 = fmaf(wj, f2.y, c1);
        }
        __syncwarp();
        out_feat[(size_t)(2 * lane) * M + mA]     = a0;
        out_feat[(size_t)(2 * lane + 1) * M + mA] = a1;
        out_feat[(size_t)(2 * lane) * M + mB]     = c0;
        out_feat[(size_t)(2 * lane + 1) * M + mB] = c1;
    }
}

// ---------------------------------------------------------------------------
extern "C" void kernel_launch(void* const* d_in, const int* in_sizes, int n_in,
                              void* d_out, int out_size) {
    const float* pc   = (const float*)d_in[0];  // (B,3,N)
    const float* qc   = (const float*)d_in[1];  // (B,3,M)
    const float* pf   = (const float*)d_in[2];  // (B,F,N)
    const float* temp = (const float*)d_in[3];  // scalar
    float* out = (float*)d_out;                 // (B,3,M) ++ (B,F,M)
    (void)in_sizes; (void)n_in; (void)out_size;

    const int smem = N * (int)sizeof(float4) + 516 + 4096 + 4096;
    cudaFuncSetAttribute(soft_projection_query,
                         cudaFuncAttributeMaxDynamicSharedMemorySize, smem);

    build_kernel<<<2 * B, 1024>>>(pc, qc);
    transpose_feat_kernel<<<dim3(N / 32, F / 32, B), dim3(32, 8)>>>(pf);
    soft_projection_query<<<dim3(37, B), 1024, smem>>>(temp, out);
}

// round 11
// speedup vs baseline: 1.1464x; 1.0211x over previous
#include <cuda_runtime.h>
#include <cfloat>
#include <math.h>

#define FULL 0xffffffffu

constexpr int B = 4;
constexpr int N = 8192;
constexpr int M = 4096;
constexpr int F = 64;
constexpr int K = 16;
constexpr float MIN_SIGMA = 1e-4f;

constexpr int   NBX   = 128;      // x-bins
constexpr int   NYB   = 16;       // y-sub-bins per x-bin
constexpr int   NBINS = NBX * NYB;
constexpr float XLO   = -3.2f;
constexpr float XW    = 0.05f;
constexpr float XINVW = 20.0f;
constexpr float YLO   = -3.2f;
constexpr float YW    = 0.4f;
constexpr float YINVW = 2.5f;
constexpr float EPSP  = 1e-4f;    // conservative pad (x gaps / y windows)

// Scratch (no allocations allowed)
__device__ float  g_featT[(size_t)B * N * F];    // (B,N,F) transposed features
__device__ float4 g_sorted[B * N];               // points, (xb,yb)-sorted
__device__ float4 g_qsorted[B * M];              // queries, (xb,yb)-sorted
__device__ int    g_start[B * (NBINS + 1)];      // point bin offsets
__device__ int    g_task[B];                     // dynamic task counters

// ---------------------------------------------------------------------------
__device__ __forceinline__ int xbinf(float x) {
    return min(NBX - 1, max(0, (int)floorf((x - XLO) * XINVW)));
}
__device__ __forceinline__ int ybinf(float y) {
    return min(NYB - 1, max(0, (int)floorf((y - YLO) * YINVW)));
}
__device__ __forceinline__ int bin2(float x, float y) {
    return xbinf(x) * NYB + ybinf(y);
}

// ---------------------------------------------------------------------------
// Fused build: one CTA per (kind, batch). smem histogram (2048 bins) +
// block scan + smem-cursor scatter. Zeroes task counters for this replay.
// ---------------------------------------------------------------------------
__global__ void __launch_bounds__(1024, 1)
build_kernel(const float* __restrict__ pc, const float* __restrict__ qc) {
    __shared__ int cnt[NBINS];
    __shared__ int cur[NBINS];
    __shared__ int wsum[32];
    const int g = blockIdx.x;            // 0..3: points, 4..7: queries
    const bool isQ = g >= B;
    const int b = isQ ? g - B : g;
    const int n = isQ ? M : N;
    const float* src = isQ ? qc + (size_t)b * 3 * M : pc + (size_t)b * 3 * N;
    float4* dst = isQ ? g_qsorted + (size_t)b * M : g_sorted + (size_t)b * N;
    const int tid = threadIdx.x;
    const int lane = tid & 31, wid = tid >> 5;

    if (g == 0 && tid < B) g_task[tid] = 0;

    for (int i = tid; i < NBINS; i += 1024) cnt[i] = 0;
    __syncthreads();
    for (int i = tid; i < n; i += 1024)
        atomicAdd(&cnt[bin2(src[i], src[n + i])], 1);
    __syncthreads();

    // block exclusive scan, 2 bins per thread
    const int a0 = cnt[2 * tid], a1 = cnt[2 * tid + 1];
    const int s = a0 + a1;
    int inc = s;
    #pragma unroll
    for (int off = 1; off < 32; off <<= 1) {
        int nb = __shfl_up_sync(FULL, inc, off);
        if (lane >= off) inc += nb;
    }
    if (lane == 31) wsum[wid] = inc;
    __syncthreads();
    if (wid == 0) {
        int v = wsum[lane];
        #pragma unroll
        for (int off = 1; off < 32; off <<= 1) {
            int nb = __shfl_up_sync(FULL, v, off);
            if (lane >= off) v += nb;
        }
        wsum[lane] = v;
    }
    __syncthreads();
    const int excl = (wid ? wsum[wid - 1] : 0) + inc - s;
    cur[2 * tid] = excl;
    cur[2 * tid + 1] = excl + a0;
    if (!isQ) {
        g_start[b * (NBINS + 1) + 2 * tid]     = excl;
        g_start[b * (NBINS + 1) + 2 * tid + 1] = excl + a0;
        if (tid == 1023) g_start[b * (NBINS + 1) + NBINS] = excl + a0 + a1;
    }
    __syncthreads();
    for (int i = tid; i < n; i += 1024) {
        const float x = src[i], y = src[n + i], z = src[2 * n + i];
        const int pos = atomicAdd(&cur[bin2(x, y)], 1);
        dst[pos] = make_float4(x, y, z, __int_as_float(i));
    }
}

// ---------------------------------------------------------------------------
__global__ void transpose_feat_kernel(const float* __restrict__ feat) {
    __shared__ float tile[32][33];
    const int b  = blockIdx.z;
    const int n0 = blockIdx.x * 32;
    const int f0 = blockIdx.y * 32;
    const int tx = threadIdx.x, ty = threadIdx.y;
    #pragma unroll
    for (int i = ty; i < 32; i += 8)
        tile[i][tx] = feat[(size_t)b * F * N + (size_t)(f0 + i) * N + (n0 + tx)];
    __syncthreads();
    #pragma unroll
    for (int i = ty; i < 32; i += 8)
        g_featT[((size_t)b * N + (n0 + i)) * F + (f0 + tx)] = tile[tx][i];
}

// ---------------------------------------------------------------------------
// Streamlined warp-cooperative top-K insert (no per-candidate threshold
// recheck; non-improving candidates are natural no-ops). Caller refreshes
// the warp-uniform threshold once per triggered chunk.
// ---------------------------------------------------------------------------
__device__ __forceinline__ void topk_insert(float s, int pidx, int lane,
                                            float& val, int& idx,
                                            float threshold, int base) {
    unsigned bal = __ballot_sync(FULL, s < threshold);
    const bool mine = (unsigned)(lane - base) < (unsigned)K;
    while (bal) {
        const int src = __ffs(bal) - 1;
        bal &= bal - 1;
        const float cs = __shfl_sync(FULL, s, src);
        const int   ci = __shfl_sync(FULL, pidx, src);
        const unsigned less = __ballot_sync(FULL, mine && (val <= cs));
        const int pos = base + __popc(less);
        const float ot = __shfl_up_sync(FULL, val, 1);
        const int   oi = __shfl_up_sync(FULL, idx, 1);
        if (mine) {
            if (lane == pos)     { val = cs; idx = ci; }
            else if (lane > pos) { val = ot; idx = oi; }
        }
    }
}

// ---------------------------------------------------------------------------
// Query kernel: one warp, TWO (x,y)-adjacent queries per dynamic task.
// Seed: 32 points at the pair's own (x,y) sub-bin (tight initial th).
// Each visited x-bin scanned as ONE contiguous y-window range.
// ---------------------------------------------------------------------------
__global__ void __launch_bounds__(1024, 1)
soft_projection_query(const float* __restrict__ temp,
                      float* __restrict__ out) {
    extern __shared__ char smraw[];
    float4* spts = (float4*)smraw;                                    // 128KB
    int*   cst = (int*)(smraw + (size_t)N * sizeof(float4));          // 2049 ints
    float* stw = (float*)(smraw + (size_t)N * sizeof(float4) + 8200);     // 4KB
    int*   sti = (int*)  (smraw + (size_t)N * sizeof(float4) + 8200 + 4096);

    const int b = blockIdx.y;
    for (int i = threadIdx.x; i < N; i += blockDim.x) spts[i] = g_sorted[b * N + i];
    for (int i = threadIdx.x; i < NBINS + 1; i += blockDim.x)
        cst[i] = g_start[b * (NBINS + 1) + i];
    __syncthreads();

    const float t = *temp;
    const float inv_sigma = 1.0f / fmaxf(t * t, MIN_SIGMA);

    const int lane = threadIdx.x & 31;
    const int warp = threadIdx.x >> 5;
    float* mysw = stw + warp * 32;
    int*   mysi = sti + warp * 32;

    float* out_pts  = out + (size_t)b * 3 * M;
    float* out_feat = out + (size_t)B * 3 * M + (size_t)b * F * M;
    const float* featb = g_featT + (size_t)b * N * F;
    const float4* qs = g_qsorted + (size_t)b * M;

    constexpr int NT = M / 2;         // 2048 tasks per batch
    while (true) {
        int pos;
        if (lane == 0) pos = atomicAdd(&g_task[b], 1);
        pos = __shfl_sync(FULL, pos, 0);
        if (pos >= NT) break;
        // center-out (x) order: longest tasks first
        const int task = (NT / 2) + ((pos & 1) ? -((pos + 1) >> 1) : (pos >> 1));

        const float4 QA = qs[2 * task];
        const float4 QB = qs[2 * task + 1];
        const int mA = __float_as_int(QA.w);
        const int mB = __float_as_int(QB.w);

        float val, thA, thB;
        int   idx;

        // ---- seed: 32 points at the pair's (x,y) sub-bin, dual bitonic ----
        const int h  = xbinf(0.5f * (QA.x + QB.x));
        const int yb = ybinf(0.5f * (QA.y + QB.y));
        const int s0 = min(cst[h * NYB + yb], N - 32);
        {
            const float4 pt = spts[s0 + lane];
            const float aX = pt.x - QA.x, aY = pt.y - QA.y, aZ = pt.z - QA.z;
            const float bX = pt.x - QB.x, bY = pt.y - QB.y, bZ = pt.z - QB.z;
            float dA = fmaf(aX, aX, fmaf(aY, aY, aZ * aZ));
            float dB = fmaf(bX, bX, fmaf(bY, bY, bZ * bZ));
            int pA = s0 + lane, pB = s0 + lane;
            #pragma unroll
            for (int k = 2; k <= 32; k <<= 1) {
                #pragma unroll
                for (int j = k >> 1; j > 0; j >>= 1) {
                    const float ovA = __shfl_xor_sync(FULL, dA, j);
                    const int   oiA = __shfl_xor_sync(FULL, pA, j);
                    const float ovB = __shfl_xor_sync(FULL, dB, j);
                    const int   oiB = __shfl_xor_sync(FULL, pB, j);
                    const bool ks = ((lane & j) == 0) == ((lane & k) == 0);
                    if (ks ? (ovA < dA) : (ovA > dA)) { dA = ovA; pA = oiA; }
                    if (ks ? (ovB < dB) : (ovB > dB)) { dB = ovB; pB = oiB; }
                }
            }
            const float dBs = __shfl_sync(FULL, dB, lane - 16);
            const int   pBs = __shfl_sync(FULL, pB, lane - 16);
            val = (lane < 16) ? dA : dBs;
            idx = (lane < 16) ? pA : pBs;
            thA = __shfl_sync(FULL, val, K - 1);
            thB = __shfl_sync(FULL, val, 16 + K - 1);
        }

        // ---- scan one contiguous range [s,e), 64-pt chunks, both queries ----
        auto scan_raw = [&](int s, int e) {
            for (int p0 = s; p0 < e; p0 += 64) {
                const int q0 = p0 + lane, q1 = p0 + lane + 32;
                float dA0 = FLT_MAX, dA1 = FLT_MAX, dB0 = FLT_MAX, dB1 = FLT_MAX;
                if (q0 < e) {
                    const float4 pt = spts[q0];
                    const float aX = pt.x - QA.x, aY = pt.y - QA.y, aZ = pt.z - QA.z;
                    const float bX = pt.x - QB.x, bY = pt.y - QB.y, bZ = pt.z - QB.z;
                    dA0 = fmaf(aX, aX, fmaf(aY, aY, aZ * aZ));
                    dB0 = fmaf(bX, bX, fmaf(bY, bY, bZ * bZ));
                }
                if (q1 < e) {
                    const float4 pt = spts[q1];
                    const float aX = pt.x - QA.x, aY = pt.y - QA.y, aZ = pt.z - QA.z;
                    const float bX = pt.x - QB.x, bY = pt.y - QB.y, bZ = pt.z - QB.z;
                    dA1 = fmaf(aX, aX, fmaf(aY, aY, aZ * aZ));
                    dB1 = fmaf(bX, bX, fmaf(bY, bY, bZ * bZ));
                }
                const bool cc = (fminf(dA0, dA1) < thA) | (fminf(dB0, dB1) < thB);
                if (__any_sync(FULL, cc)) {
                    topk_insert(dA0, q0, lane, val, idx, thA, 0);
                    topk_insert(dA1, q1, lane, val, idx, thA, 0);
                    topk_insert(dB0, q0, lane, val, idx, thB, 16);
                    topk_insert(dB1, q1, lane, val, idx, thB, 16);
                    thA = __shfl_sync(FULL, val, K - 1);
                    thB = __shfl_sync(FULL, val, 16 + K - 1);
                }
            }
        };
        // range minus the seed block [s0, s0+32)
        auto scan_range = [&](int s, int e) {
            scan_raw(s, min(e, s0));
            scan_raw(max(s, s0 + 32), e);
        };

        // one contiguous y-window scan of x-bin bx (gx^2 per query given)
        auto process_bin = [&](int bx, float gA2, float gB2) {
            const float avail = fmaxf(thA - gA2, thB - gB2);
            if (avail <= 0.0f) return;
            const float ry = sqrtf(avail) + EPSP;
            const float ylo = fminf(QA.y, QB.y) - ry;
            const float yhi = fmaxf(QA.y, QB.y) + ry;
            const int lo = max(0, min(NYB - 1, (int)floorf((ylo - YLO) * YINVW)));
            const int hi = max(0, min(NYB - 1, (int)floorf((yhi - YLO) * YINVW)));
            scan_range(cst[bx * NYB + lo], cst[bx * NYB + hi + 1]);
        };

        process_bin(h, 0.0f, 0.0f);                  // home x-bin
        for (int l = h - 1; l >= 0; l--) {           // left expansion
            const float edge = XLO + (l + 1) * XW;
            const float gA = QA.x - edge - EPSP;
            const float gB = QB.x - edge - EPSP;
            const float gA2 = (gA > 0.0f) ? gA * gA : 0.0f;
            const float gB2 = (gB > 0.0f) ? gB * gB : 0.0f;
            if (gA2 >= thA && gB2 >= thB) break;
            process_bin(l, gA2, gB2);
        }
        for (int r = h + 1; r < NBX; r++) {          // right expansion
            const float edge = XLO + r * XW;
            const float gA = edge - QA.x - EPSP;
            const float gB = edge - QB.x - EPSP;
            const float gA2 = (gA > 0.0f) ? gA * gA : 0.0f;
            const float gB2 = (gB > 0.0f) ? gB * gB : 0.0f;
            if (gA2 >= thA && gB2 >= thB) break;
            process_bin(r, gA2, gB2);
        }

        // ---- softmax per half-warp ----
        const int base = lane & 16;
        const float s_min = __shfl_sync(FULL, val, base);
        const float e = __expf(-(val - s_min) * inv_sigma);
        float esum = e;
        #pragma unroll
        for (int o = 8; o; o >>= 1) esum += __shfl_xor_sync(FULL, esum, o);
        const float w = e / esum;

        // ---- projected points ----
        const float4 gp = spts[idx];
        float wx = w * gp.x, wy = w * gp.y, wz = w * gp.z;
        #pragma unroll
        for (int o = 8; o; o >>= 1) {
            wx += __shfl_xor_sync(FULL, wx, o);
            wy += __shfl_xor_sync(FULL, wy, o);
            wz += __shfl_xor_sync(FULL, wz, o);
        }
        if (lane == 0) {
            out_pts[mA]         = wx;
            out_pts[M + mA]     = wy;
            out_pts[2 * M + mA] = wz;
        } else if (lane == 16) {
            out_pts[mB]         = wx;
            out_pts[M + mB]     = wy;
            out_pts[2 * M + mB] = wz;
        }

        // ---- features: stage (w, idx) in smem, broadcast-read ----
        const int og = __float_as_int(gp.w);
        mysw[lane] = w;
        mysi[lane] = og;
        __syncwarp();
        float a0 = 0.f, a1 = 0.f, c0 = 0.f, c1 = 0.f;
        #pragma unroll
        for (int j = 0; j < K; j++) {
            const float wj = mysw[j];
            const int   gj = mysi[j];
            const float2 f2 = *reinterpret_cast<const float2*>(
                featb + (size_t)gj * F + lane * 2);
            a0 = fmaf(wj, f2.x, a0);
            a1 = fmaf(wj, f2.y, a1);
        }
        #pragma unroll
        for (int j = 16; j < 16 + K; j++) {
            const float wj = mysw[j];
            const int   gj = mysi[j];
            const float2 f2 = *reinterpret_cast<const float2*>(
                featb + (size_t)gj * F + lane * 2);
            c0 = fmaf(wj, f2.x, c0);
            c1 = fmaf(wj, f2.y, c1);
        }
        __syncwarp();
        out_feat[(size_t)(2 * lane) * M + mA]     = a0;
        out_feat[(size_t)(2 * lane + 1) * M + mA] = a1;
        out_feat[(size_t)(2 * lane) * M + mB]     = c0;
        out_feat[(size_t)(2 * lane + 1) * M + mB] = c1;
    }
}

// ---------------------------------------------------------------------------
extern "C" void kernel_launch(void* const* d_in, const int* in_sizes, int n_in,
                              void* d_out, int out_size) {
    const float* pc   = (const float*)d_in[0];  // (B,3,N)
    const float* qc   = (const float*)d_in[1];  // (B,3,M)
    const float* pf   = (const float*)d_in[2];  // (B,F,N)
    const float* temp = (const float*)d_in[3];  // scalar
    float* out = (float*)d_out;                 // (B,3,M) ++ (B,F,M)
    (void)in_sizes; (void)n_in; (void)out_size;

    const int smem = N * (int)sizeof(float4) + 8200 + 4096 + 4096;
    cudaFuncSetAttribute(soft_projection_query,
                         cudaFuncAttributeMaxDynamicSharedMemorySize, smem);

    build_kernel<<<2 * B, 1024>>>(pc, qc);
    transpose_feat_kernel<<<dim3(N / 32, F / 32, B), dim3(32, 8)>>>(pf);
    soft_projection_query<<<dim3(37, B), 1024, smem>>>(temp, out);
}